// round 8
// baseline (speedup 1.0000x reference)
#include <cuda_runtime.h>
#include <cuda_bf16.h>
#include <cstdint>
#include <cstddef>
#include <math.h>

#define B_    128
#define T_    512
#define I_    512
#define H_    512
#define NQ_   8
#define NG    1544            // 3*512 gate cols + 8 q cols
#define NGPAD 1664            // 13 * 128

// ---------------------------------------------------------------------------
// Device scratch (static globals; no allocation)
// ---------------------------------------------------------------------------
__device__ float    g_Xpre[(size_t)T_ * B_ * NG];   // [t][b][col] x-part + bias
__device__ float    g_WxAll[(size_t)I_ * NGPAD];    // x-part weights, padded cols
__device__ float    g_WhT[(size_t)NG * H_];         // h-part weights TRANSPOSED: [col][k]
__device__ float    g_biasAll[NGPAD];
__device__ unsigned g_cnt[4][T_];                   // per-btile per-step arrival counters

// ---------------------------------------------------------------------------
// f32x2 helpers (FFMA2 = 2x fp32 FMA throughput, PTX-only)
// ---------------------------------------------------------------------------
typedef unsigned long long ull;
__device__ __forceinline__ ull pk2(float lo, float hi) {
    ull r;
    asm("mov.b64 %0, {%1, %2};" : "=l"(r) : "f"(lo), "f"(hi));
    return r;
}
__device__ __forceinline__ void fma2(ull& d, ull a, ull b) {
    asm("fma.rn.f32x2 %0, %1, %2, %0;" : "+l"(d) : "l"(a), "l"(b));
}
__device__ __forceinline__ float2 up2(ull v) {
    float lo, hi;
    asm("mov.b64 {%0, %1}, %2;" : "=f"(lo), "=f"(hi) : "l"(v));
    return make_float2(lo, hi);
}
__device__ __forceinline__ float lohi(ull v) { float2 p = up2(v); return p.x + p.y; }
__device__ __forceinline__ float sigm(float x) { return 1.0f / (1.0f + expf(-x)); }

// ---------------------------------------------------------------------------
// Pack: columns [0,512)=i  [512,1024)=g  [1024,1536)=o  [1536,1544)=qf, pad=0
//   Also zeroes the step counters (stream-ordered before rec each replay).
// ---------------------------------------------------------------------------
__global__ void pack_kernel(const float* __restrict__ Wi, const float* __restrict__ bi,
                            const float* __restrict__ Wg, const float* __restrict__ bg,
                            const float* __restrict__ Wo, const float* __restrict__ bo,
                            const float* __restrict__ Wf, const float* __restrict__ bf) {
    int idx = blockIdx.x * blockDim.x + threadIdx.x;
    if (idx < 4 * T_) ((unsigned*)g_cnt)[idx] = 0u;
    if (idx >= I_ * NGPAD) return;
    int k  = idx / NGPAD;
    int jp = idx % NGPAD;
    float vx = 0.f, vh = 0.f, vb = 0.f;
    if (jp < 512) {
        vx = Wi[k * 512 + jp];   vh = Wi[(512 + k) * 512 + jp];   vb = bi[jp];
    } else if (jp < 1024) {
        int j = jp - 512;
        vx = Wg[k * 512 + j];    vh = Wg[(512 + k) * 512 + j];    vb = bg[j];
    } else if (jp < 1536) {
        int j = jp - 1024;
        vx = Wo[k * 512 + j];    vh = Wo[(512 + k) * 512 + j];    vb = bo[j];
    } else if (jp < NG) {
        int j = jp - 1536;
        vx = Wf[k * NQ_ + j];    vh = Wf[(512 + k) * NQ_ + j];    vb = bf[j];
    }
    g_WxAll[(size_t)k * NGPAD + jp] = vx;
    if (jp < NG) g_WhT[(size_t)jp * 512 + k] = vh;     // transposed: [col][k]
    if (k == 0)  g_biasAll[jp] = vb;
}

// ---------------------------------------------------------------------------
// Precompute GEMM: g_Xpre[t][b][j] = sum_k x[b][t][k]*WxAll[k][j] + bias[j]
// ---------------------------------------------------------------------------
__global__ void __launch_bounds__(256, 2) sgemm_kernel(const float* __restrict__ A) {
    __shared__ float As[16][128];
    __shared__ float Bs[16][128];

    const int bn  = blockIdx.x;    // 0..12
    const int bm  = blockIdx.y;    // 0..511
    const int tid = threadIdx.x;

    const int arow = tid >> 2, ac4 = tid & 3;
    const int brow = tid >> 5, bc4 = tid & 31;
    const int tr   = tid >> 4, tc  = tid & 15;

    ull acc2[8][4] = {};

    const float* Ab = A + (size_t)(bm * 128) * 512;
    const float* Bb = g_WxAll + bn * 128;

    for (int k0 = 0; k0 < 512; k0 += 16) {
#pragma unroll
        for (int p = 0; p < 2; ++p) {
            int r = arow + p * 64;
            float4 v = *(const float4*)(Ab + (size_t)r * 512 + k0 + ac4 * 4);
            As[ac4 * 4 + 0][r] = v.x;
            As[ac4 * 4 + 1][r] = v.y;
            As[ac4 * 4 + 2][r] = v.z;
            As[ac4 * 4 + 3][r] = v.w;
        }
#pragma unroll
        for (int p = 0; p < 2; ++p) {
            int r = brow + p * 8;
            float4 v = *(const float4*)(Bb + (size_t)(k0 + r) * NGPAD + bc4 * 4);
            *(float4*)&Bs[r][bc4 * 4] = v;
        }
        __syncthreads();
#pragma unroll
        for (int kk = 0; kk < 16; ++kk) {
            float a[8];
            *(float4*)&a[0] = *(const float4*)&As[kk][tr * 8];
            *(float4*)&a[4] = *(const float4*)&As[kk][tr * 8 + 4];
            const ull* brw = reinterpret_cast<const ull*>(&Bs[kk][tc * 8]);
            ull b0 = brw[0], b1 = brw[1], b2 = brw[2], b3 = brw[3];
#pragma unroll
            for (int i = 0; i < 8; ++i) {
                ull as = pk2(a[i], a[i]);
                fma2(acc2[i][0], as, b0);
                fma2(acc2[i][1], as, b1);
                fma2(acc2[i][2], as, b2);
                fma2(acc2[i][3], as, b3);
            }
        }
        __syncthreads();
    }

#pragma unroll
    for (int i = 0; i < 8; ++i) {
        int m = bm * 128 + tr * 8 + i;
        int b = m >> 9;
        int t = m & 511;
        size_t obase = ((size_t)t * B_ + b) * NG;
#pragma unroll
        for (int jp = 0; jp < 4; ++jp) {
            float2 v = up2(acc2[i][jp]);
            int col = bn * 128 + tc * 8 + jp * 2;
            if (col < NG)     g_Xpre[obase + col]     = v.x + g_biasAll[col];
            if (col + 1 < NG) g_Xpre[obase + col + 1] = v.y + g_biasAll[col + 1];
        }
    }
}

// ---------------------------------------------------------------------------
// Persistent recurrent kernel: 128 CTAs x 256 threads, 1 CTA/SM.
//   CTA = btile (32 batch rows) x jtile (16 hidden cols).
//   Thread: bloc = tid>>3 (batch row), jg = tid&7 (adjacent column pair).
//   Accumulators pair over k parity -> zero dup MOVs; weight smem rows at
//   stride 516 put the 8 jg lanes on disjoint bank quads (1-phase LDS.128).
//   Sync: per-btile per-step gmem counters + 2 __syncthreads per step.
// ---------------------------------------------------------------------------
struct RecSmem {
    float wcol[48][516];   // gate/parity/jg -> k-major weights
    float wfT[8][516];     // Wf h-part rows, k-major
    float hsm[32][516];    // h_{t-1} tile
    float wfpc[16][8];     // Wfp per local col, k-major
    float qq[32][8];
    float bfp[16];
    float qp[8];
    float qa[3];
    float qb[3];
};

__global__ void __launch_bounds__(256, 1)
rec_kernel(const float* __restrict__ h0, const float* __restrict__ c0,
           const float* __restrict__ qnn_a, const float* __restrict__ qnn_b,
           const float* __restrict__ qparams, const float* __restrict__ Wfp,
           const float* __restrict__ bfp_g, float* __restrict__ out) {
    extern __shared__ char smraw[];
    RecSmem& S = *reinterpret_cast<RecSmem*>(smraw);

    const int tid   = threadIdx.x;
    const int btile = blockIdx.x >> 5;   // 0..3
    const int jtile = blockIdx.x & 31;   // 0..31
    const int b0    = btile * 32;
    const int j0    = jtile * 16;

    // ---- one-time persistent weight loads (coalesced: g_WhT is k-major) ----
    for (int i = tid; i < 48 * 512; i += 256) {
        int row = i >> 9;
        int k   = i & 511;
        int g   = row >> 4;
        int r   = row & 15;
        int p   = r >> 3;
        int jgl = r & 7;
        int col = g * 512 + j0 + 2 * jgl + p;
        S.wcol[row][k] = g_WhT[(size_t)col * 512 + k];
    }
    for (int i = tid; i < 8 * 512; i += 256) {
        int r = i >> 9, k = i & 511;
        S.wfT[r][k] = g_WhT[(size_t)(1536 + r) * 512 + k];
    }
    for (int i = tid; i < 16 * 8; i += 256) {
        int col = i >> 3, k2 = i & 7;
        S.wfpc[col][k2] = Wfp[k2 * 512 + j0 + col];
    }
    if (tid < 16) S.bfp[tid] = bfp_g[j0 + tid];
    if (tid < 8)  S.qp[tid]  = qparams[tid];
    if (tid < 3)  { S.qa[tid] = qnn_a[tid]; S.qb[tid] = qnn_b[tid]; }

    const int bloc = tid >> 3;
    const int jg   = tid & 7;
    const int jcol = j0 + 2 * jg;
    const int brow = b0 + bloc;

    float2 cr = *(const float2*)&c0[(size_t)brow * 512 + jcol];

    // prefetch x-parts for t=0
    float2 pI, pG, pO; float pqx;
    {
        const size_t xr = (size_t)brow * NG;
        pI  = *(const float2*)&g_Xpre[xr + 0 * 512 + jcol];
        pG  = *(const float2*)&g_Xpre[xr + 1 * 512 + jcol];
        pO  = *(const float2*)&g_Xpre[xr + 2 * 512 + jcol];
        pqx = g_Xpre[xr + 1536 + jg];
    }

    __syncthreads();

    const float* w_i0 = S.wcol[0 * 16 + jg];
    const float* w_i1 = S.wcol[0 * 16 + 8 + jg];
    const float* w_g0 = S.wcol[1 * 16 + jg];
    const float* w_g1 = S.wcol[1 * 16 + 8 + jg];
    const float* w_o0 = S.wcol[2 * 16 + jg];
    const float* w_o1 = S.wcol[2 * 16 + 8 + jg];
    const float* wqr  = S.wfT[jg];
    float* hrow = S.hsm[bloc];

    volatile unsigned* cnt = (volatile unsigned*)g_cnt[btile];

    for (int t = 0; t < T_; ++t) {
        // ---- stage h_{t-1} row: 8 lanes of this bloc cooperate ----
        {
            const float* hb;
            if (t == 0) hb = h0 + (size_t)brow * 512;
            else        hb = out + ((size_t)brow * 512 + (t - 1)) * 512;
#pragma unroll
            for (int c = 0; c < 4; ++c) {
                int off = jg * 16 + c * 128;
                float4 v0 = __ldcg((const float4*)(hb + off));
                float4 v1 = __ldcg((const float4*)(hb + off + 4));
                float4 v2 = __ldcg((const float4*)(hb + off + 8));
                float4 v3 = __ldcg((const float4*)(hb + off + 12));
                *(float4*)&hrow[off]      = v0;
                *(float4*)&hrow[off + 4]  = v1;
                *(float4*)&hrow[off + 8]  = v2;
                *(float4*)&hrow[off + 12] = v3;
            }
        }
        // prefetch next step's x-parts (static data) to overlap with GEMM
        float2 nI, nG, nO; float nqx;
        if (t + 1 < T_) {
            const size_t xr = ((size_t)(t + 1) * B_ + brow) * NG;
            nI  = *(const float2*)&g_Xpre[xr + 0 * 512 + jcol];
            nG  = *(const float2*)&g_Xpre[xr + 1 * 512 + jcol];
            nO  = *(const float2*)&g_Xpre[xr + 2 * 512 + jcol];
            nqx = g_Xpre[xr + 1536 + jg];
        }
        __syncwarp();

        // ---- fused gate GEMM + q dot: accumulators pair over k parity ----
        ull ai0 = 0, ai1 = 0, ag0 = 0, ag1 = 0, ao0 = 0, ao1 = 0, q2 = 0;
#pragma unroll 8
        for (int k = 0; k < 512; k += 4) {
            ulonglong2 hp = *(const ulonglong2*)&hrow[k];
            ulonglong2 w;
            w = *(const ulonglong2*)&w_i0[k]; fma2(ai0, hp.x, w.x); fma2(ai0, hp.y, w.y);
            w = *(const ulonglong2*)&w_i1[k]; fma2(ai1, hp.x, w.x); fma2(ai1, hp.y, w.y);
            w = *(const ulonglong2*)&w_g0[k]; fma2(ag0, hp.x, w.x); fma2(ag0, hp.y, w.y);
            w = *(const ulonglong2*)&w_g1[k]; fma2(ag1, hp.x, w.x); fma2(ag1, hp.y, w.y);
            w = *(const ulonglong2*)&w_o0[k]; fma2(ao0, hp.x, w.x); fma2(ao0, hp.y, w.y);
            w = *(const ulonglong2*)&w_o1[k]; fma2(ao1, hp.x, w.x); fma2(ao1, hp.y, w.y);
            w = *(const ulonglong2*)&wqr[k];  fma2(q2,  hp.x, w.x); fma2(q2,  hp.y, w.y);
        }

        // ---- quantum forget gate chain (one q element per thread) ----
        float qv = lohi(q2) + pqx;
#pragma unroll
        for (int r = 0; r < 3; ++r) qv = tanhf(qv * S.qa[r] + S.qb[r]);
        S.qq[bloc][jg] = qv + S.qp[jg];
        __syncwarp();

        // ---- f = sigmoid(qq @ Wfp + bfp), k-paired over NQ=8 ----
        ull f0p = pk2(S.bfp[2 * jg], 0.f);
        ull f1p = pk2(S.bfp[2 * jg + 1], 0.f);
        ulonglong2 qA = *(const ulonglong2*)&S.qq[bloc][0];
        ulonglong2 qB = *(const ulonglong2*)&S.qq[bloc][4];
        {
            ulonglong2 wa = *(const ulonglong2*)&S.wfpc[2 * jg][0];
            ulonglong2 wb = *(const ulonglong2*)&S.wfpc[2 * jg][4];
            fma2(f0p, qA.x, wa.x); fma2(f0p, qA.y, wa.y);
            fma2(f0p, qB.x, wb.x); fma2(f0p, qB.y, wb.y);
        }
        {
            ulonglong2 wa = *(const ulonglong2*)&S.wfpc[2 * jg + 1][0];
            ulonglong2 wb = *(const ulonglong2*)&S.wfpc[2 * jg + 1][4];
            fma2(f1p, qA.x, wa.x); fma2(f1p, qA.y, wa.y);
            fma2(f1p, qB.x, wb.x); fma2(f1p, qB.y, wb.y);
        }
        float f0 = sigm(lohi(f0p));
        float f1 = sigm(lohi(f1p));

        // ---- gates, cell, hidden ----
        float i0 = sigm(pI.x + lohi(ai0)),  i1 = sigm(pI.y + lohi(ai1));
        float g0 = tanhf(pG.x + lohi(ag0)), g1 = tanhf(pG.y + lohi(ag1));
        float o0 = sigm(pO.x + lohi(ao0)),  o1 = sigm(pO.y + lohi(ao1));

        cr.x = f0 * cr.x + i0 * g0;
        cr.y = f1 * cr.y + i1 * g1;
        float h0v = o0 * tanhf(cr.x);
        float h1v = o1 * tanhf(cr.y);

        *(float2*)&out[((size_t)brow * 512 + t) * 512 + jcol] = make_float2(h0v, h1v);

        pI = nI; pG = nG; pO = nO; pqx = nqx;

        // ---- per-btile step barrier (skip after last step) ----
        if (t + 1 < T_) {
            __syncthreads();
            if (tid == 0) {
                __threadfence();
                atomicAdd(&g_cnt[btile][t], 1u);
                while (cnt[t] < 32u) { __nanosleep(32); }
                __threadfence();
            }
            __syncthreads();
        }
    }
}

// ---------------------------------------------------------------------------
extern "C" void kernel_launch(void* const* d_in, const int* in_sizes, int n_in,
                              void* d_out, int out_size) {
    const float* x       = (const float*)d_in[0];
    const float* h0      = (const float*)d_in[1];
    const float* c0      = (const float*)d_in[2];
    const float* Wi      = (const float*)d_in[3];
    const float* bi      = (const float*)d_in[4];
    const float* Wg      = (const float*)d_in[5];
    const float* bg      = (const float*)d_in[6];
    const float* Wo      = (const float*)d_in[7];
    const float* bo      = (const float*)d_in[8];
    const float* Wf      = (const float*)d_in[9];
    const float* bf      = (const float*)d_in[10];
    const float* qnn_a   = (const float*)d_in[11];
    const float* qnn_b   = (const float*)d_in[12];
    const float* qparams = (const float*)d_in[13];
    const float* Wfp     = (const float*)d_in[14];
    const float* bfp     = (const float*)d_in[15];
    float* out = (float*)d_out;

    cudaFuncSetAttribute(rec_kernel, cudaFuncAttributeMaxDynamicSharedMemorySize,
                         (int)sizeof(RecSmem));

    pack_kernel<<<(I_ * NGPAD + 255) / 256, 256>>>(Wi, bi, Wg, bg, Wo, bo, Wf, bf);
    sgemm_kernel<<<dim3(13, 512), 256>>>(x);
    rec_kernel<<<128, 256, sizeof(RecSmem)>>>(h0, c0, qnn_a, qnn_b, qparams,
                                              Wfp, bfp, out);
}